// round 9
// baseline (speedup 1.0000x reference)
#include <cuda_runtime.h>
#include <cuda_fp16.h>
#include <math.h>

#define BATCH 4096
__device__ float g_feat[BATCH * 192];
// prepped fp16 weights: [c][k_lin], k_lin = tap*VPAD + v  (96 x 256 each)
__device__ __half g_wP[96 * 256], g_wL[96 * 256];

typedef unsigned int u32;

__device__ __forceinline__ u32 sm32(const void* p) {
    u32 a;
    asm("{ .reg .u64 t; cvta.to.shared.u64 t, %1; cvt.u32.u64 %0, t; }"
        : "=r"(a) : "l"(p));
    return a;
}
__device__ __forceinline__ void ldsm4(u32* r, u32 a) {
    asm volatile("ldmatrix.sync.aligned.m8n8.x4.shared.b16 {%0,%1,%2,%3}, [%4];"
                 : "=r"(r[0]), "=r"(r[1]), "=r"(r[2]), "=r"(r[3]) : "r"(a));
}
__device__ __forceinline__ void mma16816(float* d, const u32* a, u32 b0, u32 b1) {
    asm volatile(
        "mma.sync.aligned.m16n8k16.row.col.f32.f16.f16.f32 "
        "{%0,%1,%2,%3}, {%4,%5,%6,%7}, {%8,%9}, {%0,%1,%2,%3};"
        : "+f"(d[0]), "+f"(d[1]), "+f"(d[2]), "+f"(d[3])
        : "r"(a[0]), "r"(a[1]), "r"(a[2]), "r"(a[3]), "r"(b0), "r"(b1));
}
__device__ __forceinline__ void cp16(u32 dst, const void* src) {
    asm volatile("cp.async.ca.shared.global [%0], [%1], 16;" :: "r"(dst), "l"(src));
}
__device__ __forceinline__ void cp_commit() {
    asm volatile("cp.async.commit_group;" ::: "memory");
}
__device__ __forceinline__ void cp_wait0() {
    asm volatile("cp.async.wait_group 0;" ::: "memory");
}

// ---------------------------------------------------------------------------
// weight prep: fp32 [96][VU][TAPS] -> fp16 [96][256], k_lin = tap*VPAD + v
// ---------------------------------------------------------------------------
template <int VU, int TAPS, int VPAD, bool PRO>
__global__ void prep_w(const float* __restrict__ w) {
    int u = blockIdx.x * 256 + threadIdx.x;
    if (u >= 96 * 256) return;
    int c = u >> 8, k = u & 255;
    int tap = k / VPAD, v = k - tap * VPAD;
    float val = (v < VU) ? w[(c * VU + v) * TAPS + tap] : 0.f;
    (PRO ? g_wP : g_wL)[u] = __float2half_rn(val);
}

__global__ void zero_feat_kernel() {
    int i = blockIdx.x * 1024 + threadIdx.x;
    if (i < BATCH * 192) g_feat[i] = 0.f;
}

// ---------------------------------------------------------------------------
// Persistent conv via mma.sync m16n8k16 fp16 (x, w both fp16; measured final
// rel_err ~4e-5 << 1e-3). Tile covers NSAMP sample-sections of SECT rows.
//   NSAMP=1: warp wid owns positions t0 + [wid*16*MW, +16*MW)  (m steps 16)
//   NSAMP=2: warp wid owns rows [wid*16,+16) in BOTH sections (m steps SECT,
//            frag m belongs to sample b0+m; epilogue keeps them separate)
// x staged time-major rows (XSTR bytes); tap shift = +tap rows on A address.
// cp.async stages next tile's fp32 into smem scratch during the mma loop.
// ---------------------------------------------------------------------------
template <int NTH, int VU, int VPAD, int CHK, int TAPS, int LEN, int OUT,
          int SECT, int MW, int NSAMP, int NTPER, int FEAT_OFF, int XSTR,
          bool PRO>
__global__ __launch_bounds__(NTH, 1)
void conv_mma(const float* __restrict__ x, const float* __restrict__ bias)
{
    constexpr int NW    = NTH / 32;
    constexpr int TILE  = NW * 16 * MW;           // positions per tile (NSAMP=1)
    constexpr int WSTEP = (NSAMP == 1) ? 16 * MW : 16;
    constexpr int MSTEP = (NSAMP == 2) ? SECT : 16;
    constexpr int ROWS  = NSAMP * SECT;
    constexpr int WSTR  = VPAD * TAPS * 2 + 16;   // 528
    constexpr int OFF_W = 0;
    constexpr int WSZ   = 96 * WSTR;              // 50688
    constexpr int OFF_X = WSZ;
    constexpr int XBUF  = ROWS * XSTR;
    constexpr int OFF_S = OFF_X + 2 * XBUF;       // fp32 scratch
    constexpr int SSZ   = VU * ROWS * 4;
    constexpr int OFF_B = OFF_S + SSZ;
    constexpr int NTILES = (NSAMP == 2) ? BATCH / 2 : BATCH * NTPER;
    constexpr int CPS   = SECT / 4;               // 16B chunks per section row-run
    constexpr int NCP   = (VU * NSAMP * CPS + NTH - 1) / NTH;
    constexpr int NCV   = (VU * ROWS + NTH - 1) / NTH;

    extern __shared__ char sm[];
    const u32 sb  = sm32(sm);
    const int tid = threadIdx.x, wid = tid >> 5, lane = tid & 31;

    const __half* wsrc = PRO ? g_wP : g_wL;
    for (int u = tid; u < 96 * 256; u += NTH) {
        int c = u >> 8, k = u & 255;
        *(__half*)(sm + OFF_W + c * WSTR + k * 2) = wsrc[u];
    }
    // zero x region once (covers vocab pad bytes inside rows + halo rows)
    for (int u = tid; u < (2 * XBUF) / 16; u += NTH)
        *reinterpret_cast<float4*>(sm + OFF_X + u * 16) =
            make_float4(0.f, 0.f, 0.f, 0.f);
    if (tid < 96) ((float*)(sm + OFF_B))[tid] = bias[tid];

    auto issue_cp = [&](int g) {
        int b0 = (NSAMP == 2) ? 2 * g : g / NTPER;
        int t0 = (NSAMP == 2) ? 0 : (g - b0 * NTPER) * TILE;
        int valid = LEN - t0; if (valid > SECT) valid = SECT;
        int nch = valid >> 2;
        #pragma unroll
        for (int i = 0; i < NCP; i++) {
            int u = tid + i * NTH;
            if (u < VU * NSAMP * CPS) {
                int v = u / (NSAMP * CPS);
                int rem = u - v * (NSAMP * CPS);
                int s = rem / CPS, c = rem - s * CPS;
                if (c < nch)
                    cp16(sb + (u32)(OFF_S + (v * ROWS + s * SECT + c * 4) * 4),
                         x + ((size_t)(b0 + s) * VU + v) * LEN + t0 + c * 4);
            }
        }
        cp_commit();
    };
    auto cvt = [&](int g, int nb) {
        int b0 = (NSAMP == 2) ? 2 * g : g / NTPER;
        int t0 = (NSAMP == 2) ? 0 : (g - b0 * NTPER) * TILE;
        int valid = LEN - t0; if (valid > SECT) valid = SECT;
        const float* sc = (const float*)(sm + OFF_S);
        char* xp = sm + OFF_X + nb * XBUF;
        #pragma unroll
        for (int i = 0; i < NCV; i++) {
            int u = tid + i * NTH;
            if (u < VU * ROWS) {
                int v = u / ROWS, rem = u - v * ROWS;
                int s = rem / SECT, r = rem - s * SECT;
                float val = (r < valid) ? sc[v * ROWS + s * SECT + r] : 0.f;
                *(__half*)(xp + (s * SECT + r) * XSTR + v * 2) =
                    __float2half_rn(val);
            }
        }
    };

    const int g0 = blockIdx.x;
    if (g0 < NTILES) issue_cp(g0);
    cp_wait0();
    __syncthreads();
    if (g0 < NTILES) cvt(g0, 0);
    __syncthreads();

    const u32 a_lo = (u32)((lane & 15) * XSTR + (lane >> 4) * 16);
    const u32 b_lo = (u32)(((lane & 7) + ((lane >> 4) << 3)) * WSTR
                           + ((lane >> 3) & 1) * 16);
    const u32 wb = sb + (u32)OFF_W + b_lo;

    int buf = 0;
    for (int g = g0; g < NTILES; g += gridDim.x) {
        const int gn = g + (int)gridDim.x;
        if (gn < NTILES) issue_cp(gn);   // async: overlaps the mma loop

        float acc[MW][12][4];
        #pragma unroll
        for (int m = 0; m < MW; m++)
            #pragma unroll
            for (int j = 0; j < 12; j++)
                #pragma unroll
                for (int e = 0; e < 4; e++) acc[m][j][e] = 0.f;

        const u32 xab = sb + (u32)(OFF_X + buf * XBUF)
                      + (u32)(wid * WSTEP) * XSTR + a_lo;

        #pragma unroll
        for (int tap = 0; tap < TAPS; tap++) {
            #pragma unroll
            for (int ch = 0; ch < CHK; ch++) {
                const u32 aoff = (u32)(tap * XSTR + ch * 32);
                u32 ah[MW][4];
                #pragma unroll
                for (int m = 0; m < MW; m++)
                    ldsm4(ah[m], xab + aoff + (u32)(m * MSTEP) * XSTR);
                const u32 wk = (u32)((tap * VPAD + ch * 16) * 2);
                #pragma unroll
                for (int p = 0; p < 6; p++) {
                    u32 bf[4];
                    ldsm4(bf, wb + (u32)(p * 16 * WSTR) + wk);
                    #pragma unroll
                    for (int m = 0; m < MW; m++) {
                        mma16816(acc[m][2 * p],     ah[m], bf[0], bf[1]);
                        mma16816(acc[m][2 * p + 1], ah[m], bf[2], bf[3]);
                    }
                }
            }
        }

        // ---- epilogue: per-m fused mask + max + bias + ReLU -> atomicMax
        {
            const int b0 = (NSAMP == 2) ? 2 * g : g / NTPER;
            const int t0 = (NSAMP == 2) ? 0 : (g - b0 * NTPER) * TILE;
            const int row = lane >> 2;
            const float NEG = -1e30f;
            #pragma unroll
            for (int m = 0; m < MW; m++) {
                const int b = b0 + ((NSAMP == 2) ? m : 0);
                const int pbase = (NSAMP == 2) ? wid * 16
                                               : t0 + wid * WSTEP + m * 16;
                const int p0 = pbase + row;
                float mx[24];
                #pragma unroll
                for (int j = 0; j < 12; j++)
                    #pragma unroll
                    for (int e = 0; e < 2; e++) {
                        float v = NEG;
                        if (p0 < OUT)     v = fmaxf(v, acc[m][j][e]);
                        if (p0 + 8 < OUT) v = fmaxf(v, acc[m][j][e + 2]);
                        mx[2 * j + e] = v;
                    }
                #pragma unroll
                for (int off = 4; off <= 16; off <<= 1)
                    #pragma unroll
                    for (int q = 0; q < 24; q++)
                        mx[q] = fmaxf(mx[q],
                                      __shfl_xor_sync(0xffffffffu, mx[q], off));
                if (lane < 4) {
                    #pragma unroll
                    for (int j = 0; j < 12; j++)
                        #pragma unroll
                        for (int e = 0; e < 2; e++) {
                            int c = j * 8 + lane * 2 + e;
                            float bb = ((const float*)(sm + OFF_B))[c];
                            float val = fmaxf(mx[2 * j + e] + bb, 0.f);
                            atomicMax(reinterpret_cast<int*>(
                                          &g_feat[(size_t)b * 192 + FEAT_OFF + c]),
                                      __float_as_int(val));
                        }
                }
            }
        }

        cp_wait0();
        __syncthreads();                 // all mma reads of buf done; scratch ready
        if (gn < NTILES) cvt(gn, buf ^ 1);
        __syncthreads();                 // buf^1 visible before next mma
        buf ^= 1;
    }
}

// ---------------------------------------------------------------------------
// Per-sample: x = feat.reshape(6,32); gram = x^T x; L2-normalize; dot w_aff.
// ---------------------------------------------------------------------------
__global__ __launch_bounds__(256)
void gram_readout_kernel(const float* __restrict__ w_aff,
                         const float* __restrict__ b_aff,
                         float* __restrict__ out, int B)
{
    __shared__ float s_w[1024];
    __shared__ float s_f[8][192];
    const int tid  = threadIdx.x;
    const int warp = tid >> 5, lane = tid & 31;
    const int b = blockIdx.x * 8 + warp;

    for (int u = tid; u < 1024; u += 256) s_w[u] = w_aff[u];
    if (b < B)
        for (int u = lane; u < 192; u += 32) s_f[warp][u] = g_feat[(size_t)b * 192 + u];
    __syncthreads();
    if (b >= B) return;

    float xk[6];
    #pragma unroll
    for (int i = 0; i < 6; i++) xk[i] = s_f[warp][i * 32 + lane];

    float s1 = 0.f, s2 = 0.f;
    #pragma unroll 4
    for (int j = 0; j < 32; j++) {
        float g = 0.f;
        #pragma unroll
        for (int i = 0; i < 6; i++) g = fmaf(s_f[warp][i * 32 + j], xk[i], g);
        s2 = fmaf(g, g, s2);
        s1 = fmaf(g, s_w[j * 32 + lane], s1);
    }
    #pragma unroll
    for (int off = 16; off > 0; off >>= 1) {
        s1 += __shfl_xor_sync(0xffffffffu, s1, off);
        s2 += __shfl_xor_sync(0xffffffffu, s2, off);
    }
    if (lane == 0) out[b] = s1 / (sqrtf(s2) + 1e-12f) + b_aff[0];
}

// ---------------------------------------------------------------------------

extern "C" void kernel_launch(void* const* d_in, const int* in_sizes, int n_in,
                              void* d_out, int out_size)
{
    const float* protein = (const float*)d_in[0];
    const float* ligand  = (const float*)d_in[1];
    const float* w_pro   = (const float*)d_in[2];
    const float* b_pro   = (const float*)d_in[3];
    const float* w_lig   = (const float*)d_in[4];
    const float* b_lig   = (const float*)d_in[5];
    const float* w_aff   = (const float*)d_in[6];
    const float* b_aff   = (const float*)d_in[7];

    int seen96 = 0;
    for (int i = 0; i < n_in; i++) {
        long long s = in_sizes[i];
        const float* p = (const float*)d_in[i];
        if      (s == (long long)BATCH * 25 * 1000) protein = p;
        else if (s == (long long)BATCH * 64 * 100)  ligand  = p;
        else if (s == 96LL * 25 * 8)                w_pro   = p;
        else if (s == 96LL * 64 * 4)                w_lig   = p;
        else if (s == 1024LL)                       w_aff   = p;
        else if (s == 96LL) { if (seen96++ == 0) b_pro = p; else b_lig = p; }
        else if (s == 1LL)                          b_aff   = p;
    }

    float* out = (float*)d_out;

    // ligand : 256thr, 2 samples/tile (NSAMP=2, SECT=128, MW=2) -> regs<=255
    // protein: 512thr, MW=1 TILE=256 NTPER=4 -> regs fit under the 128 cap
    auto kL = conv_mma<256, 64, 64, 4, 4, 100, 97, 128, 2, 2, 1, 0, 144, false>;
    auto kP = conv_mma<512, 25, 32, 2, 8, 1000, 993, 264, 1, 1, 4, 96, 80, true>;

    // smem sizes (mirror kernel constexprs)
    constexpr int SMEM_L = 96 * 528 + 2 * (256 * 144) + 64 * 256 * 4 + 384; // 190336
    constexpr int SMEM_P = 96 * 528 + 2 * (264 * 80)  + 25 * 264 * 4 + 384; // 119712

    cudaFuncSetAttribute(kL, cudaFuncAttributeMaxDynamicSharedMemorySize, SMEM_L);
    cudaFuncSetAttribute(kP, cudaFuncAttributeMaxDynamicSharedMemorySize, SMEM_P);

    zero_feat_kernel<<<(BATCH * 192 + 1023) / 1024, 1024>>>();
    prep_w<64, 4, 64, false><<<96, 256>>>(w_lig);
    prep_w<25, 8, 32, true><<<96, 256>>>(w_pro);
    kL<<<148, 256, SMEM_L>>>(ligand, b_lig);
    kP<<<148, 512, SMEM_P>>>(protein, b_pro);
    gram_readout_kernel<<<BATCH / 8, 256>>>(w_aff, b_aff, out, BATCH);
}

// round 10
// speedup vs baseline: 1.1694x; 1.1694x over previous
#include <cuda_runtime.h>
#include <cuda_fp16.h>
#include <math.h>

#define BATCH 4096
__device__ float g_feat[BATCH * 192];
// prepped fp16 weights: [c][k_lin], k_lin = tap*VPAD + v  (96 x 256 each)
__device__ __half g_wP[96 * 256], g_wL[96 * 256];

typedef unsigned int u32;

__device__ __forceinline__ u32 sm32(const void* p) {
    u32 a;
    asm("{ .reg .u64 t; cvta.to.shared.u64 t, %1; cvt.u32.u64 %0, t; }"
        : "=r"(a) : "l"(p));
    return a;
}
__device__ __forceinline__ void ldsm4(u32* r, u32 a) {
    asm volatile("ldmatrix.sync.aligned.m8n8.x4.shared.b16 {%0,%1,%2,%3}, [%4];"
                 : "=r"(r[0]), "=r"(r[1]), "=r"(r[2]), "=r"(r[3]) : "r"(a));
}
__device__ __forceinline__ void mma16816(float* d, const u32* a, u32 b0, u32 b1) {
    asm volatile(
        "mma.sync.aligned.m16n8k16.row.col.f32.f16.f16.f32 "
        "{%0,%1,%2,%3}, {%4,%5,%6,%7}, {%8,%9}, {%0,%1,%2,%3};"
        : "+f"(d[0]), "+f"(d[1]), "+f"(d[2]), "+f"(d[3])
        : "r"(a[0]), "r"(a[1]), "r"(a[2]), "r"(a[3]), "r"(b0), "r"(b1));
}
__device__ __forceinline__ void cp16(u32 dst, const void* src) {
    asm volatile("cp.async.ca.shared.global [%0], [%1], 16;" :: "r"(dst), "l"(src));
}
__device__ __forceinline__ void cp_commit() {
    asm volatile("cp.async.commit_group;" ::: "memory");
}
__device__ __forceinline__ void cp_wait0() {
    asm volatile("cp.async.wait_group 0;" ::: "memory");
}

// ---------------------------------------------------------------------------
// weight prep: fp32 [96][VU][TAPS] -> fp16 [96][256], k_lin = tap*VPAD + v
// ---------------------------------------------------------------------------
template <int VU, int TAPS, int VPAD, bool PRO>
__global__ void prep_w(const float* __restrict__ w) {
    int u = blockIdx.x * 256 + threadIdx.x;
    if (u >= 96 * 256) return;
    int c = u >> 8, k = u & 255;
    int tap = k / VPAD, v = k - tap * VPAD;
    float val = (v < VU) ? w[(c * VU + v) * TAPS + tap] : 0.f;
    (PRO ? g_wP : g_wL)[u] = __float2half_rn(val);
}

__global__ void zero_feat_kernel() {
    int i = blockIdx.x * 1024 + threadIdx.x;
    if (i < BATCH * 192) g_feat[i] = 0.f;
}

// ---------------------------------------------------------------------------
// Persistent conv via mma.sync m16n8k16 fp16 (x, w fp16; measured rel_err
// ~4e-5 << 1e-3). 512 threads = 16 warps = two 8-warp GROUPS (GRP = wid/8):
//   GS=true  (ligand):  GRP selects the sample-section; warp owns rows
//                       (wid&7)*16 of its section; MW=1; all 12 n8 ch-frags.
//   GS=false (protein): GRP selects channels [GRP*48,+48) (NCF=6 frags);
//                       warp owns positions t0+(wid&7)*32 (MW=2).
// Either way acc = 48 floats -> no spill under the 128-reg cap.
// x staged time-major rows (XSTR bytes, conflict-free mod 128); tap shift =
// +tap rows on the A address; 8 zeroed halo rows terminate every buffer.
// cp.async stages the next tile's fp32 into smem scratch during the mma loop.
// ---------------------------------------------------------------------------
template <int VU, int VPAD, int CHK, int TAPS, int LEN, int OUT, int SECT,
          int MW, bool GS, int NTPER, int FEAT_OFF, int XSTR, bool PRO>
__global__ __launch_bounds__(512, 1)
void conv_mma(const float* __restrict__ x, const float* __restrict__ bias)
{
    constexpr int NTH   = 512;
    constexpr int NCF   = GS ? 12 : 6;            // n8 channel-frags per warp
    constexpr int NSAMP = GS ? 2 : 1;
    constexpr int TILE  = GS ? SECT : 8 * 16 * MW;  // 256 positions (protein)
    constexpr int ROWS  = NSAMP * SECT;
    constexpr int XROWS = ROWS + 8;               // zeroed halo rows
    constexpr int WSTR  = VPAD * TAPS * 2 + 16;   // 528
    constexpr int OFF_W = 0;
    constexpr int WSZ   = 96 * WSTR;              // 50688
    constexpr int OFF_X = WSZ;
    constexpr int XBUF  = XROWS * XSTR;
    constexpr int OFF_S = OFF_X + 2 * XBUF;       // fp32 scratch
    constexpr int SSZ   = VU * ROWS * 4;
    constexpr int OFF_B = OFF_S + SSZ;
    constexpr int NTILES = GS ? BATCH / 2 : BATCH * NTPER;
    constexpr int CPS   = SECT / 4;               // 16B chunks per section row
    constexpr int NCP   = (VU * NSAMP * CPS + NTH - 1) / NTH;
    constexpr int NCV   = (VU * ROWS + NTH - 1) / NTH;

    extern __shared__ char sm[];
    const u32 sb  = sm32(sm);
    const int tid = threadIdx.x, wid = tid >> 5, lane = tid & 31;
    const int grp = wid >> 3, wpos = wid & 7;

    const __half* wsrc = PRO ? g_wP : g_wL;
    for (int u = tid; u < 96 * 256; u += NTH) {
        int c = u >> 8, k = u & 255;
        *(__half*)(sm + OFF_W + c * WSTR + k * 2) = wsrc[u];
    }
    // zero x region once (covers vocab pad bytes inside rows + halo rows)
    for (int u = tid; u < (2 * XBUF) / 16; u += NTH)
        *reinterpret_cast<float4*>(sm + OFF_X + u * 16) =
            make_float4(0.f, 0.f, 0.f, 0.f);
    if (tid < 96) ((float*)(sm + OFF_B))[tid] = bias[tid];

    auto issue_cp = [&](int g) {
        int b0 = GS ? 2 * g : g / NTPER;
        int t0 = GS ? 0 : (g - b0 * NTPER) * TILE;
        int valid = LEN - t0; if (valid > SECT) valid = SECT;
        int nch = valid >> 2;
        #pragma unroll
        for (int i = 0; i < NCP; i++) {
            int u = tid + i * NTH;
            if (u < VU * NSAMP * CPS) {
                int v = u / (NSAMP * CPS);
                int rem = u - v * (NSAMP * CPS);
                int s = rem / CPS, c = rem - s * CPS;
                if (c < nch)
                    cp16(sb + (u32)(OFF_S + (v * ROWS + s * SECT + c * 4) * 4),
                         x + ((size_t)(b0 + s) * VU + v) * LEN + t0 + c * 4);
            }
        }
        cp_commit();
    };
    auto cvt = [&](int g, int nb) {
        int b0 = GS ? 2 * g : g / NTPER;
        int t0 = GS ? 0 : (g - b0 * NTPER) * TILE;
        int valid = LEN - t0; if (valid > SECT) valid = SECT;
        const float* sc = (const float*)(sm + OFF_S);
        char* xp = sm + OFF_X + nb * XBUF;
        #pragma unroll
        for (int i = 0; i < NCV; i++) {
            int u = tid + i * NTH;
            if (u < VU * ROWS) {
                int v = u / ROWS, rem = u - v * ROWS;
                int s = rem / SECT, r = rem - s * SECT;
                float val = (r < valid) ? sc[v * ROWS + s * SECT + r] : 0.f;
                *(__half*)(xp + (s * SECT + r) * XSTR + v * 2) =
                    __float2half_rn(val);
            }
        }
    };

    const int g0 = blockIdx.x;
    if (g0 < NTILES) issue_cp(g0);
    cp_wait0();
    __syncthreads();
    if (g0 < NTILES) cvt(g0, 0);
    __syncthreads();

    const u32 a_lo = (u32)((lane & 15) * XSTR + (lane >> 4) * 16);
    const u32 b_lo = (u32)(((lane & 7) + ((lane >> 4) << 3)) * WSTR
                           + ((lane >> 3) & 1) * 16);
    // channel base: ligand = all 96; protein = group's 48 rows
    const u32 wb = sb + (u32)OFF_W + b_lo
                 + (GS ? 0u : (u32)(grp * NCF * 8 * WSTR));
    // position-row base inside the x buffer
    const int prow = GS ? (grp * SECT + wpos * 16) : (wpos * 16 * MW);

    int buf = 0;
    for (int g = g0; g < NTILES; g += gridDim.x) {
        const int gn = g + (int)gridDim.x;
        if (gn < NTILES) issue_cp(gn);   // async: overlaps the mma loop

        float acc[MW][NCF][4];
        #pragma unroll
        for (int m = 0; m < MW; m++)
            #pragma unroll
            for (int j = 0; j < NCF; j++)
                #pragma unroll
                for (int e = 0; e < 4; e++) acc[m][j][e] = 0.f;

        const u32 xab = sb + (u32)(OFF_X + buf * XBUF)
                      + (u32)prow * XSTR + a_lo;

        #pragma unroll
        for (int tap = 0; tap < TAPS; tap++) {
            #pragma unroll
            for (int ch = 0; ch < CHK; ch++) {
                const u32 aoff = (u32)(tap * XSTR + ch * 32);
                u32 ah[MW][4];
                #pragma unroll
                for (int m = 0; m < MW; m++)
                    ldsm4(ah[m], xab + aoff + (u32)(m * 16 * XSTR));
                const u32 wk = (u32)((tap * VPAD + ch * 16) * 2);
                #pragma unroll
                for (int p = 0; p < NCF / 2; p++) {
                    u32 bf[4];
                    ldsm4(bf, wb + (u32)(p * 16 * WSTR) + wk);
                    #pragma unroll
                    for (int m = 0; m < MW; m++) {
                        mma16816(acc[m][2 * p],     ah[m], bf[0], bf[1]);
                        mma16816(acc[m][2 * p + 1], ah[m], bf[2], bf[3]);
                    }
                }
            }
        }

        // ---- epilogue: fused mask + max + bias + ReLU -> global atomicMax
        {
            const int b0 = GS ? 2 * g : g / NTPER;
            const int t0 = GS ? 0 : (g - b0 * NTPER) * TILE;
            const int b  = b0 + (GS ? grp : 0);
            const int row = lane >> 2;
            const float NEG = -1e30f;
            float mx[2 * NCF];
            #pragma unroll
            for (int j = 0; j < NCF; j++)
                #pragma unroll
                for (int e = 0; e < 2; e++) {
                    float v = NEG;
                    #pragma unroll
                    for (int m = 0; m < MW; m++) {
                        const int p0 = (GS ? wpos * 16
                                           : t0 + wpos * 16 * MW + m * 16) + row;
                        if (p0 < OUT)     v = fmaxf(v, acc[m][j][e]);
                        if (p0 + 8 < OUT) v = fmaxf(v, acc[m][j][e + 2]);
                    }
                    mx[2 * j + e] = v;
                }
            #pragma unroll
            for (int off = 4; off <= 16; off <<= 1)
                #pragma unroll
                for (int q = 0; q < 2 * NCF; q++)
                    mx[q] = fmaxf(mx[q], __shfl_xor_sync(0xffffffffu, mx[q], off));
            if (lane < 4) {
                #pragma unroll
                for (int j = 0; j < NCF; j++)
                    #pragma unroll
                    for (int e = 0; e < 2; e++) {
                        int c = (GS ? 0 : grp * NCF * 8) + j * 8 + lane * 2 + e;
                        float bb = ((const float*)(sm + OFF_B))[c];
                        float val = fmaxf(mx[2 * j + e] + bb, 0.f);
                        atomicMax(reinterpret_cast<int*>(
                                      &g_feat[(size_t)b * 192 + FEAT_OFF + c]),
                                  __float_as_int(val));
                    }
            }
        }

        cp_wait0();
        __syncthreads();                 // all mma reads of buf done; scratch ready
        if (gn < NTILES) cvt(gn, buf ^ 1);
        __syncthreads();                 // buf^1 visible before next mma
        buf ^= 1;
    }
}

// ---------------------------------------------------------------------------
// Per-sample: x = feat.reshape(6,32); gram = x^T x; L2-normalize; dot w_aff.
// ---------------------------------------------------------------------------
__global__ __launch_bounds__(256)
void gram_readout_kernel(const float* __restrict__ w_aff,
                         const float* __restrict__ b_aff,
                         float* __restrict__ out, int B)
{
    __shared__ float s_w[1024];
    __shared__ float s_f[8][192];
    const int tid  = threadIdx.x;
    const int warp = tid >> 5, lane = tid & 31;
    const int b = blockIdx.x * 8 + warp;

    for (int u = tid; u < 1024; u += 256) s_w[u] = w_aff[u];
    if (b < B)
        for (int u = lane; u < 192; u += 32) s_f[warp][u] = g_feat[(size_t)b * 192 + u];
    __syncthreads();
    if (b >= B) return;

    float xk[6];
    #pragma unroll
    for (int i = 0; i < 6; i++) xk[i] = s_f[warp][i * 32 + lane];

    float s1 = 0.f, s2 = 0.f;
    #pragma unroll 4
    for (int j = 0; j < 32; j++) {
        float g = 0.f;
        #pragma unroll
        for (int i = 0; i < 6; i++) g = fmaf(s_f[warp][i * 32 + j], xk[i], g);
        s2 = fmaf(g, g, s2);
        s1 = fmaf(g, s_w[j * 32 + lane], s1);
    }
    #pragma unroll
    for (int off = 16; off > 0; off >>= 1) {
        s1 += __shfl_xor_sync(0xffffffffu, s1, off);
        s2 += __shfl_xor_sync(0xffffffffu, s2, off);
    }
    if (lane == 0) out[b] = s1 / (sqrtf(s2) + 1e-12f) + b_aff[0];
}

// ---------------------------------------------------------------------------

extern "C" void kernel_launch(void* const* d_in, const int* in_sizes, int n_in,
                              void* d_out, int out_size)
{
    const float* protein = (const float*)d_in[0];
    const float* ligand  = (const float*)d_in[1];
    const float* w_pro   = (const float*)d_in[2];
    const float* b_pro   = (const float*)d_in[3];
    const float* w_lig   = (const float*)d_in[4];
    const float* b_lig   = (const float*)d_in[5];
    const float* w_aff   = (const float*)d_in[6];
    const float* b_aff   = (const float*)d_in[7];

    int seen96 = 0;
    for (int i = 0; i < n_in; i++) {
        long long s = in_sizes[i];
        const float* p = (const float*)d_in[i];
        if      (s == (long long)BATCH * 25 * 1000) protein = p;
        else if (s == (long long)BATCH * 64 * 100)  ligand  = p;
        else if (s == 96LL * 25 * 8)                w_pro   = p;
        else if (s == 96LL * 64 * 4)                w_lig   = p;
        else if (s == 1024LL)                       w_aff   = p;
        else if (s == 96LL) { if (seen96++ == 0) b_pro = p; else b_lig = p; }
        else if (s == 1LL)                          b_aff   = p;
    }

    float* out = (float*)d_out;

    // ligand : GS=true  SECT=128 MW=1 (2 samples/tile, 12 ch-frags/warp)
    // protein: GS=false SECT=264 MW=2 NTPER=4 (TILE=256, 6 ch-frags/warp)
    auto kL = conv_mma<64, 64, 4, 4, 100, 97, 128, 1, true, 1, 0, 144, false>;
    auto kP = conv_mma<25, 32, 2, 8, 1000, 993, 264, 2, false, 4, 96, 80, true>;

    // smem sizes (mirror kernel constexprs)
    constexpr int SMEM_L = 50688 + 2 * (264 * 144) + 64 * 256 * 4 + 384; // 192640
    constexpr int SMEM_P = 50688 + 2 * (272 * 80)  + 25 * 264 * 4 + 384; // 120992

    cudaFuncSetAttribute(kL, cudaFuncAttributeMaxDynamicSharedMemorySize, SMEM_L);
    cudaFuncSetAttribute(kP, cudaFuncAttributeMaxDynamicSharedMemorySize, SMEM_P);

    zero_feat_kernel<<<(BATCH * 192 + 1023) / 1024, 1024>>>();
    prep_w<64, 4, 64, false><<<96, 256>>>(w_lig);
    prep_w<25, 8, 32, true><<<96, 256>>>(w_pro);
    kL<<<148, 512, SMEM_L>>>(ligand, b_lig);
    kP<<<148, 512, SMEM_P>>>(protein, b_pro);
    gram_readout_kernel<<<BATCH / 8, 256>>>(w_aff, b_aff, out, BATCH);
}